// round 5
// baseline (speedup 1.0000x reference)
#include <cuda_runtime.h>
#include <cuda_fp16.h>
#include <cstdint>

// Shapes (fixed by the problem)
#define BB 8192            // batch (GEMM M)
#define II 512             // input dim
#define FF 64              // freqs
#define OO 512             // output dim (GEMM N)
#define KK (II * FF)       // GEMM K = 32768

// GEMM tiling
#define BM 128
#define BN 128
#define BK 64              // one i-column of x per K iteration
#define A_STRIDE 72        // halves (128B row + 16B pad -> conflict-free ldmatrix)
#define W_STRIDE 136       // halves
#define KITERS (KK / BK)   // 512

// ---- device scratch (allocation-free rule: __device__ globals) ----
__device__ __half g_W[KK * OO];      // 32 MB: W[k,o] = inv_f * beta[f,o] * lamb[i,o]
__device__ float  g_xT[II * BB];     // 16 MB: x transposed [I][B]
__device__ float  g_biasp[OO];       // folded bias
__device__ float  g_invf[FF];
__device__ float  g_meanf[FF];

// ---------------- P0: per-frequency stats ----------------
__global__ void k_stats(const float* __restrict__ freqs, const float* __restrict__ phases) {
    int f = threadIdx.x;
    if (f < FF) {
        float w = freqs[f], p = phases[f];
        float m = expf(-0.5f * w * w) * sinf(p);
        float v = 0.5f - 0.5f * expf(-2.0f * w * w) * cosf(2.0f * p) - m * m;
        g_meanf[f] = m;
        g_invf[f]  = rsqrtf(1e-3f + v);
    }
}

// ---------------- P1: build W (fp16) ----------------
__global__ void k_buildW(const float* __restrict__ beta, const float* __restrict__ lamb) {
    int idx = blockIdx.x * blockDim.x + threadIdx.x;   // [0, KK*OO)
    int o = idx & (OO - 1);
    int k = idx >> 9;            // OO = 512
    int f = k & (FF - 1);
    int i = k >> 6;              // FF = 64
    float w = g_invf[f] * beta[f * OO + o] * lamb[i * OO + o];
    g_W[idx] = __float2half(w);
}

// ---------------- P2: folded bias ----------------
__global__ void k_biasp(const float* __restrict__ beta, const float* __restrict__ lamb,
                        const float* __restrict__ bias) {
    int o = blockIdx.x * blockDim.x + threadIdx.x;
    if (o < OO) {
        float s1 = 0.f;
        #pragma unroll
        for (int f = 0; f < FF; f++) s1 += g_meanf[f] * g_invf[f] * beta[f * OO + o];
        float s2 = 0.f;
        for (int i = 0; i < II; i++) s2 += lamb[i * OO + o];
        g_biasp[o] = bias[o] - s1 * s2;
    }
}

// ---------------- P3: transpose x -> xT[I][B] ----------------
__global__ void k_transpose(const float* __restrict__ x) {
    __shared__ float tile[32][33];
    int i0 = blockIdx.x * 32;
    int b0 = blockIdx.y * 32;
    int tx = threadIdx.x, ty = threadIdx.y;
    #pragma unroll
    for (int j = 0; j < 4; j++)
        tile[ty + j * 8][tx] = x[(size_t)(b0 + ty + j * 8) * II + i0 + tx];
    __syncthreads();
    #pragma unroll
    for (int j = 0; j < 4; j++)
        g_xT[(size_t)(i0 + ty + j * 8) * BB + b0 + tx] = tile[tx][ty + j * 8];
}

// ---------------- main fused GEMM ----------------
__device__ __forceinline__ void cp_async16(void* s, const void* g) {
    uint32_t sa = (uint32_t)__cvta_generic_to_shared(s);
    asm volatile("cp.async.cg.shared.global [%0], [%1], 16;\n" :: "r"(sa), "l"(g));
}
__device__ __forceinline__ uint32_t smem_u32(const void* p) {
    return (uint32_t)__cvta_generic_to_shared(p);
}

__device__ __forceinline__ void issue_tile(int k, int t, int bm0, int bn0,
                                           __half* sW, float* sx) {
    int buf = k & 1;
    const __half* gW = g_W + (size_t)k * (BK * OO) + bn0;
    __half* sWb = sW + buf * (BK * W_STRIDE);
    #pragma unroll
    for (int j = 0; j < 4; j++) {
        int c = t + 256 * j;           // 0..1023 chunks of 16B (64 rows x 16 segs)
        int row = c >> 4;
        int seg = c & 15;
        cp_async16(sWb + row * W_STRIDE + seg * 8, gW + row * OO + seg * 8);
    }
    if (t < 32) {
        cp_async16(sx + buf * BM + t * 4, g_xT + (size_t)k * BB + bm0 + t * 4);
    }
    asm volatile("cp.async.commit_group;\n" ::: "memory");
}

__global__ __launch_bounds__(256, 2)
void k_gemm(const float* __restrict__ freqs, const float* __restrict__ phases,
            float* __restrict__ out) {
    extern __shared__ char smem_raw[];
    __half* sA = (__half*)smem_raw;                     // [2][BM][A_STRIDE]
    __half* sW = sA + 2 * BM * A_STRIDE;                // [2][BK][W_STRIDE]
    float*  sx = (float*)(sW + 2 * BK * W_STRIDE);      // [2][BM]
    float* swf = sx + 2 * BM;                           // [FF]
    float* spf = swf + FF;                              // [FF]

    const int t    = threadIdx.x;
    const int lane = t & 31;
    const int warp = t >> 5;
    const int bm0  = blockIdx.y * BM;
    const int bn0  = blockIdx.x * BN;
    const int wm0  = (warp >> 2) * 64;   // 2 warp-rows
    const int wn0  = (warp & 3) * 32;    // 4 warp-cols

    if (t < FF) { swf[t] = freqs[t]; spf[t] = phases[t]; }

    float acc[4][4][4];
    #pragma unroll
    for (int mt = 0; mt < 4; mt++)
        #pragma unroll
        for (int nt = 0; nt < 4; nt++)
            #pragma unroll
            for (int r = 0; r < 4; r++) acc[mt][nt][r] = 0.f;

    issue_tile(0, t, bm0, bn0, sW, sx);

    for (int k = 0; k < KITERS; k++) {
        const int buf = k & 1;
        asm volatile("cp.async.wait_group 0;\n" ::: "memory");
        __syncthreads();   // all warps done with iter k-1; buffers (k+1)&1 free

        if (k + 1 < KITERS) issue_tile(k + 1, t, bm0, bn0, sW, sx);

        // ---- generate A tile: sin(w_f * x + p_f), 32 sins/thread ----
        {
            int r  = t >> 1;
            int fb = (t & 1) * 32;
            float xv = sx[buf * BM + r];
            __half* aRow = sA + buf * BM * A_STRIDE + r * A_STRIDE;
            #pragma unroll
            for (int ff = 0; ff < 32; ff += 2) {
                int f = fb + ff;
                float s0 = __sinf(fmaf(swf[f],     xv, spf[f]));
                float s1 = __sinf(fmaf(swf[f + 1], xv, spf[f + 1]));
                *(__half2*)(aRow + f) = __floats2half2_rn(s0, s1);
            }
        }
        __syncthreads();

        // ---- MMA over the BK=64 slab (4 k16 steps) ----
        const __half* Ab = sA + buf * BM * A_STRIDE;
        const __half* Wb = sW + buf * BK * W_STRIDE;
        #pragma unroll
        for (int ks = 0; ks < 4; ks++) {
            uint32_t af[4][4];
            #pragma unroll
            for (int mt = 0; mt < 4; mt++) {
                uint32_t addr = smem_u32(Ab + (size_t)(wm0 + mt * 16 + (lane & 15)) * A_STRIDE
                                            + ks * 16 + (lane >> 4) * 8);
                asm volatile("ldmatrix.sync.aligned.m8n8.x4.shared.b16 {%0,%1,%2,%3}, [%4];\n"
                    : "=r"(af[mt][0]), "=r"(af[mt][1]), "=r"(af[mt][2]), "=r"(af[mt][3])
                    : "r"(addr));
            }
            uint32_t bf[4][2];
            #pragma unroll
            for (int np = 0; np < 2; np++) {
                uint32_t addr = smem_u32(Wb + (size_t)(ks * 16 + (lane & 15)) * W_STRIDE
                                            + wn0 + np * 16 + (lane >> 4) * 8);
                uint32_t b0, b1, b2, b3;
                asm volatile("ldmatrix.sync.aligned.m8n8.x4.trans.shared.b16 {%0,%1,%2,%3}, [%4];\n"
                    : "=r"(b0), "=r"(b1), "=r"(b2), "=r"(b3) : "r"(addr));
                bf[np * 2][0] = b0; bf[np * 2][1] = b1;
                bf[np * 2 + 1][0] = b2; bf[np * 2 + 1][1] = b3;
            }
            #pragma unroll
            for (int mt = 0; mt < 4; mt++)
                #pragma unroll
                for (int nt = 0; nt < 4; nt++) {
                    asm volatile(
                        "mma.sync.aligned.m16n8k16.row.col.f32.f16.f16.f32 "
                        "{%0,%1,%2,%3}, {%4,%5,%6,%7}, {%8,%9}, {%0,%1,%2,%3};\n"
                        : "+f"(acc[mt][nt][0]), "+f"(acc[mt][nt][1]),
                          "+f"(acc[mt][nt][2]), "+f"(acc[mt][nt][3])
                        : "r"(af[mt][0]), "r"(af[mt][1]), "r"(af[mt][2]), "r"(af[mt][3]),
                          "r"(bf[nt][0]), "r"(bf[nt][1]));
                }
        }
    }

    // ---- epilogue: add folded bias, store fp32 ----
    #pragma unroll
    for (int mt = 0; mt < 4; mt++) {
        int row = bm0 + wm0 + mt * 16 + (lane >> 2);
        #pragma unroll
        for (int nt = 0; nt < 4; nt++) {
            int col = bn0 + wn0 + nt * 8 + (lane & 3) * 2;
            float b0 = g_biasp[col], b1 = g_biasp[col + 1];
            float2 v0 = make_float2(acc[mt][nt][0] + b0, acc[mt][nt][1] + b1);
            float2 v1 = make_float2(acc[mt][nt][2] + b0, acc[mt][nt][3] + b1);
            *(float2*)(out + (size_t)row * OO + col)       = v0;
            *(float2*)(out + (size_t)(row + 8) * OO + col) = v1;
        }
    }
}

// ---------------- launch ----------------
extern "C" void kernel_launch(void* const* d_in, const int* in_sizes, int n_in,
                              void* d_out, int out_size) {
    const float* x      = (const float*)d_in[0];  // [8192, 512]
    const float* freqs  = (const float*)d_in[1];  // [1,1,64]
    const float* phases = (const float*)d_in[2];  // [1,1,64]
    const float* beta   = (const float*)d_in[3];  // [64, 512]
    const float* lamb   = (const float*)d_in[4];  // [512, 512]
    const float* bias   = (const float*)d_in[5];  // [512]
    float* out = (float*)d_out;                   // [8192, 512] fp32

    k_stats<<<1, 64>>>(freqs, phases);
    k_buildW<<<(KK * OO) / 256, 256>>>(beta, lamb);
    k_biasp<<<2, 256>>>(beta, lamb, bias);
    {
        dim3 tb(32, 8), tg(II / 32, BB / 32);
        k_transpose<<<tg, tb>>>(x);
    }

    const size_t smem_bytes =
        (size_t)(2 * BM * A_STRIDE + 2 * BK * W_STRIDE) * sizeof(__half)
        + (size_t)(2 * BM + 2 * FF) * sizeof(float);   // 73,216 B
    cudaFuncSetAttribute(k_gemm, cudaFuncAttributeMaxDynamicSharedMemorySize,
                         (int)smem_bytes);
    dim3 grid(OO / BN, BB / BM);   // (4, 64)
    k_gemm<<<grid, 256, smem_bytes>>>(freqs, phases, out);
}

// round 7
// speedup vs baseline: 1.0149x; 1.0149x over previous
#include <cuda_runtime.h>
#include <cuda_fp16.h>
#include <cstdint>

// Shapes (fixed by the problem)
#define BB 8192            // batch (GEMM M)
#define II 512             // input dim
#define FF 64              // freqs
#define OO 512             // output dim (GEMM N)
#define KK (II * FF)       // GEMM K = 32768

// GEMM tiling
#define BM 128
#define BN 256
#define BK 64              // one i-column of x per K iteration
#define NTHREADS 512
#define A_STRIDE 72        // halves: 144B rows, conflict-free ldmatrix
#define W_STRIDE 264       // halves: 528B rows (256 + 8 pad)
#define KITERS (KK / BK)   // 512

// ---- device scratch (allocation-free rule: __device__ globals) ----
__device__ __half g_W[(size_t)KK * OO]; // 32 MB: W[k][o] = inv_f*beta[f,o]*lamb[i,o]
__device__ float  g_xT[(size_t)II * BB];// 16 MB: x transposed [I][B]
__device__ float  g_biasp[OO];          // folded bias
__device__ float  g_invf[FF];
__device__ float  g_meanf[FF];

// ---------------- P0: per-frequency stats ----------------
__global__ void k_stats(const float* __restrict__ freqs, const float* __restrict__ phases) {
    int f = threadIdx.x;
    if (f < FF) {
        float w = freqs[f], p = phases[f];
        float m = expf(-0.5f * w * w) * sinf(p);
        float v = 0.5f - 0.5f * expf(-2.0f * w * w) * cosf(2.0f * p) - m * m;
        g_meanf[f] = m;
        g_invf[f]  = rsqrtf(1e-3f + v);
    }
}

// ---------------- P1: build W (fp16), [K][O] ----------------
__global__ void k_buildW(const float* __restrict__ beta, const float* __restrict__ lamb) {
    int idx = blockIdx.x * blockDim.x + threadIdx.x;   // [0, KK*OO)
    int o = idx & (OO - 1);
    int k = idx >> 9;            // OO = 512
    int f = k & (FF - 1);
    int i = k >> 6;              // FF = 64
    float w = g_invf[f] * beta[f * OO + o] * lamb[i * OO + o];
    g_W[idx] = __float2half(w);
}

// ---------------- P2: folded bias ----------------
__global__ void k_biasp(const float* __restrict__ beta, const float* __restrict__ lamb,
                        const float* __restrict__ bias) {
    int o = blockIdx.x * blockDim.x + threadIdx.x;
    if (o < OO) {
        float s1 = 0.f;
        #pragma unroll
        for (int f = 0; f < FF; f++) s1 += g_meanf[f] * g_invf[f] * beta[f * OO + o];
        float s2 = 0.f;
        for (int i = 0; i < II; i++) s2 += lamb[i * OO + o];
        g_biasp[o] = bias[o] - s1 * s2;
    }
}

// ---------------- P3: transpose x -> xT[I][B] ----------------
__global__ void k_transpose(const float* __restrict__ x) {
    __shared__ float tile[32][33];
    int i0 = blockIdx.x * 32;
    int b0 = blockIdx.y * 32;
    int tx = threadIdx.x, ty = threadIdx.y;
    #pragma unroll
    for (int j = 0; j < 4; j++)
        tile[ty + j * 8][tx] = x[(size_t)(b0 + ty + j * 8) * II + i0 + tx];
    __syncthreads();
    #pragma unroll
    for (int j = 0; j < 4; j++)
        g_xT[(size_t)(i0 + ty + j * 8) * BB + b0 + tx] = tile[tx][ty + j * 8];
}

// ---------------- helpers ----------------
__device__ __forceinline__ void cp_async16(void* s, const void* g) {
    uint32_t sa = (uint32_t)__cvta_generic_to_shared(s);
    asm volatile("cp.async.cg.shared.global [%0], [%1], 16;\n" :: "r"(sa), "l"(g));
}
__device__ __forceinline__ uint32_t smem_u32(const void* p) {
    return (uint32_t)__cvta_generic_to_shared(p);
}

__device__ __forceinline__ void issue_tile(int k, int t, int bm0, int bn0,
                                           __half* sW, float* sx) {
    int buf = k & 1;
    const __half* gW = g_W + (size_t)k * (BK * OO) + bn0;
    __half* sWb = sW + buf * (BK * W_STRIDE);
    #pragma unroll
    for (int j = 0; j < 4; j++) {
        int c = t + NTHREADS * j;      // 0..2047: 64 rows x 32 chunks of 16B
        int row = c >> 5;
        int seg = c & 31;
        cp_async16(sWb + row * W_STRIDE + seg * 8, gW + (size_t)row * OO + seg * 8);
    }
    if (t < 32) {
        cp_async16(sx + buf * BM + t * 4, g_xT + (size_t)k * BB + bm0 + t * 4);
    }
    asm volatile("cp.async.commit_group;\n" ::: "memory");
}

__global__ __launch_bounds__(NTHREADS, 1)
void k_gemm(const float* __restrict__ freqs, const float* __restrict__ phases,
            float* __restrict__ out) {
    extern __shared__ char smem_raw[];
    __half* sA = (__half*)smem_raw;                     // [2][BM][A_STRIDE]
    __half* sW = sA + 2 * BM * A_STRIDE;                // [2][BK][W_STRIDE]
    float*  sx = (float*)(sW + 2 * BK * W_STRIDE);      // [2][BM]
    float* swf = sx + 2 * BM;                           // [FF]
    float* spf = swf + FF;                              // [FF]

    const int t    = threadIdx.x;
    const int lane = t & 31;
    const int warp = t >> 5;                 // 0..15
    const int bm0  = blockIdx.y * BM;
    const int bn0  = blockIdx.x * BN;
    const int wm0  = (warp >> 2) * 32;       // 4 warp-rows of 32
    const int wn0  = (warp & 3) * 64;        // 4 warp-cols of 64

    if (t < FF) { swf[t] = freqs[t]; spf[t] = phases[t]; }

    float acc[2][8][4];
    #pragma unroll
    for (int mt = 0; mt < 2; mt++)
        #pragma unroll
        for (int nt = 0; nt < 8; nt++)
            #pragma unroll
            for (int r = 0; r < 4; r++) acc[mt][nt][r] = 0.f;

    issue_tile(0, t, bm0, bn0, sW, sx);

    for (int k = 0; k < KITERS; k++) {
        const int buf = k & 1;
        asm volatile("cp.async.wait_group 0;\n" ::: "memory");
        __syncthreads();   // tile k landed; buffer (k+1)&1 free

        if (k + 1 < KITERS) issue_tile(k + 1, t, bm0, bn0, sW, sx);

        // ---- generate A tile: sin(w_f*x + p_f), 16 sins/thread ----
        {
            int r  = t >> 2;                 // A row
            int fb = (t & 3) * 16;           // 16-freq block
            float xv = sx[buf * BM + r];
            __half* aRow = sA + buf * BM * A_STRIDE + r * A_STRIDE + fb;
            __half2 h[8];
            #pragma unroll
            for (int j = 0; j < 8; j++) {
                int f = fb + 2 * j;
                float s0 = __sinf(fmaf(swf[f],     xv, spf[f]));
                float s1 = __sinf(fmaf(swf[f + 1], xv, spf[f + 1]));
                h[j] = __floats2half2_rn(s0, s1);
            }
            *(uint4*)(aRow)     = *(uint4*)(h);
            *(uint4*)(aRow + 8) = *(uint4*)(h + 4);
        }
        __syncthreads();

        // ---- MMA over the BK=64 slab (4 k16 steps) ----
        const __half* Ab = sA + buf * BM * A_STRIDE;
        const __half* Wb = sW + buf * BK * W_STRIDE;
        #pragma unroll
        for (int ks = 0; ks < 4; ks++) {
            uint32_t af[2][4];
            #pragma unroll
            for (int mt = 0; mt < 2; mt++) {
                uint32_t addr = smem_u32(Ab + (size_t)(wm0 + mt * 16 + (lane & 15)) * A_STRIDE
                                            + ks * 16 + (lane >> 4) * 8);
                asm volatile("ldmatrix.sync.aligned.m8n8.x4.shared.b16 {%0,%1,%2,%3}, [%4];\n"
                    : "=r"(af[mt][0]), "=r"(af[mt][1]), "=r"(af[mt][2]), "=r"(af[mt][3])
                    : "r"(addr));
            }
            uint32_t bf[8][2];
            #pragma unroll
            for (int np = 0; np < 4; np++) {
                uint32_t addr = smem_u32(Wb + (size_t)(ks * 16 + (lane & 15)) * W_STRIDE
                                            + wn0 + np * 16 + (lane >> 4) * 8);
                uint32_t b0, b1, b2, b3;
                asm volatile("ldmatrix.sync.aligned.m8n8.x4.trans.shared.b16 {%0,%1,%2,%3}, [%4];\n"
                    : "=r"(b0), "=r"(b1), "=r"(b2), "=r"(b3) : "r"(addr));
                bf[np * 2][0] = b0;     bf[np * 2][1] = b1;
                bf[np * 2 + 1][0] = b2; bf[np * 2 + 1][1] = b3;
            }
            #pragma unroll
            for (int mt = 0; mt < 2; mt++)
                #pragma unroll
                for (int nt = 0; nt < 8; nt++) {
                    asm volatile(
                        "mma.sync.aligned.m16n8k16.row.col.f32.f16.f16.f32 "
                        "{%0,%1,%2,%3}, {%4,%5,%6,%7}, {%8,%9}, {%0,%1,%2,%3};\n"
                        : "+f"(acc[mt][nt][0]), "+f"(acc[mt][nt][1]),
                          "+f"(acc[mt][nt][2]), "+f"(acc[mt][nt][3])
                        : "r"(af[mt][0]), "r"(af[mt][1]), "r"(af[mt][2]), "r"(af[mt][3]),
                          "r"(bf[nt][0]), "r"(bf[nt][1]));
                }
        }
    }

    // ---- epilogue: add folded bias, store fp32 ----
    #pragma unroll
    for (int mt = 0; mt < 2; mt++) {
        int row = bm0 + wm0 + mt * 16 + (lane >> 2);
        #pragma unroll
        for (int nt = 0; nt < 8; nt++) {
            int col = bn0 + wn0 + nt * 8 + (lane & 3) * 2;
            float b0 = g_biasp[col], b1 = g_biasp[col + 1];
            float2 v0 = make_float2(acc[mt][nt][0] + b0, acc[mt][nt][1] + b1);
            float2 v1 = make_float2(acc[mt][nt][2] + b0, acc[mt][nt][3] + b1);
            *(float2*)(out + (size_t)row * OO + col)       = v0;
            *(float2*)(out + (size_t)(row + 8) * OO + col) = v1;
        }
    }
}

// ---------------- launch ----------------
extern "C" void kernel_launch(void* const* d_in, const int* in_sizes, int n_in,
                              void* d_out, int out_size) {
    const float* x      = (const float*)d_in[0];  // [8192, 512]
    const float* freqs  = (const float*)d_in[1];  // [1,1,64]
    const float* phases = (const float*)d_in[2];  // [1,1,64]
    const float* beta   = (const float*)d_in[3];  // [64, 512]
    const float* lamb   = (const float*)d_in[4];  // [512, 512]
    const float* bias   = (const float*)d_in[5];  // [512]
    float* out = (float*)d_out;                   // [8192, 512] fp32

    k_stats<<<1, 64>>>(freqs, phases);
    k_buildW<<<(KK * OO) / 256, 256>>>(beta, lamb);
    k_biasp<<<2, 256>>>(beta, lamb, bias);
    {
        dim3 tb(32, 8), tg(II / 32, BB / 32);
        k_transpose<<<tg, tb>>>(x);
    }

    const size_t smem_bytes =
        (size_t)(2 * BM * A_STRIDE + 2 * BK * W_STRIDE) * sizeof(__half)
        + (size_t)(2 * BM + 2 * FF) * sizeof(float);   // 105,984 B
    cudaFuncSetAttribute(k_gemm, cudaFuncAttributeMaxDynamicSharedMemorySize,
                         (int)smem_bytes);
    dim3 grid(OO / BN, BB / BM);   // (2, 64) = 128 CTAs
    k_gemm<<<grid, NTHREADS, smem_bytes>>>(freqs, phases, out);
}

// round 8
// speedup vs baseline: 1.2332x; 1.2151x over previous
#include <cuda_runtime.h>
#include <cuda_fp16.h>
#include <cstdint>

// Shapes (fixed by the problem)
#define BB 8192            // batch (GEMM M)
#define II 512             // input dim
#define FF 64              // freqs
#define OO 512             // output dim (GEMM N)
#define KK (II * FF)       // GEMM K = 32768

// GEMM tiling
#define BM 128
#define BN 256
#define BK 64              // one i-column of x per K iteration
#define NTHREADS 512
#define A_STRIDE 72        // halves: 144B rows, conflict-free ldmatrix
#define W_STRIDE 264       // halves: 528B rows (256 + 8 pad)
#define KITERS (KK / BK)   // 512
#define WSTAGES 3          // W triple-buffered (A-gen overlaps mma)

// ---- device scratch (allocation-free rule: __device__ globals) ----
__device__ __half g_W[(size_t)KK * OO]; // 32 MB: W[k][o] = inv_f*beta[f,o]*lamb[i,o]
__device__ float  g_xT[(size_t)II * BB];// 16 MB: x transposed [I][B]
__device__ float  g_biasp[OO];          // folded bias

// ---------------- merged prologue ----------------
// blocks [0,4096):    build W (16 halves / thread)
// blocks [4096,8192): transpose x -> xT
// blocks [8192,8194): folded bias
__global__ void k_prep(const float* __restrict__ x,
                       const float* __restrict__ freqs,
                       const float* __restrict__ phases,
                       const float* __restrict__ beta,
                       const float* __restrict__ lamb,
                       const float* __restrict__ bias) {
    const int bx = blockIdx.x;
    const int t  = threadIdx.x;

    if (bx < 4096) {
        // ---- buildW ----
        __shared__ float sinv[FF];
        if (t < FF) {
            float w = freqs[t], p = phases[t];
            float m = expf(-0.5f * w * w) * sinf(p);
            float v = 0.5f - 0.5f * expf(-2.0f * w * w) * cosf(2.0f * p) - m * m;
            sinv[t] = rsqrtf(1e-3f + v);
        }
        __syncthreads();
        size_t base = ((size_t)bx * 256 + t) * 16;   // 16 consecutive o, same k
        int k = (int)(base >> 9);
        int o = (int)(base & 511);
        int f = k & (FF - 1);
        int i = k >> 6;
        float inv = sinv[f];
        const float4* b4 = (const float4*)(beta + (size_t)f * OO + o);
        const float4* l4 = (const float4*)(lamb + (size_t)i * OO + o);
        __half2 h[8];
        #pragma unroll
        for (int j = 0; j < 4; j++) {
            float4 bb = b4[j], ll = l4[j];
            h[2 * j]     = __floats2half2_rn(inv * bb.x * ll.x, inv * bb.y * ll.y);
            h[2 * j + 1] = __floats2half2_rn(inv * bb.z * ll.z, inv * bb.w * ll.w);
        }
        *(uint4*)(g_W + base)     = *(uint4*)(h);
        *(uint4*)(g_W + base + 8) = *(uint4*)(h + 4);
    } else if (bx < 8192) {
        // ---- transpose ----
        __shared__ float tile[32][33];
        int bx2 = bx - 4096;
        int i0 = (bx2 & 15) * 32;
        int b0 = (bx2 >> 4) * 32;
        int tx = t & 31, ty = t >> 5;
        #pragma unroll
        for (int j = 0; j < 4; j++)
            tile[ty + j * 8][tx] = x[(size_t)(b0 + ty + j * 8) * II + i0 + tx];
        __syncthreads();
        #pragma unroll
        for (int j = 0; j < 4; j++)
            g_xT[(size_t)(i0 + ty + j * 8) * BB + b0 + tx] = tile[tx][ty + j * 8];
    } else {
        // ---- folded bias ----
        __shared__ float smv[FF];
        if (t < FF) {
            float w = freqs[t], p = phases[t];
            float m = expf(-0.5f * w * w) * sinf(p);
            float v = 0.5f - 0.5f * expf(-2.0f * w * w) * cosf(2.0f * p) - m * m;
            smv[t] = m * rsqrtf(1e-3f + v);
        }
        __syncthreads();
        int o = (bx - 8192) * 256 + t;
        float s1 = 0.f;
        #pragma unroll
        for (int f = 0; f < FF; f++) s1 += smv[f] * beta[f * OO + o];
        float s2 = 0.f;
        for (int i = 0; i < II; i++) s2 += lamb[(size_t)i * OO + o];
        g_biasp[o] = bias[o] - s1 * s2;
    }
}

// ---------------- helpers ----------------
__device__ __forceinline__ void cp_async16(void* s, const void* g) {
    uint32_t sa = (uint32_t)__cvta_generic_to_shared(s);
    asm volatile("cp.async.cg.shared.global [%0], [%1], 16;\n" :: "r"(sa), "l"(g));
}
__device__ __forceinline__ uint32_t smem_u32(const void* p) {
    return (uint32_t)__cvta_generic_to_shared(p);
}

__device__ __forceinline__ void issueW(int k, int t, int bn0, __half* sW) {
    const int buf = k % WSTAGES;
    const __half* gW = g_W + (size_t)k * (BK * OO) + bn0;
    __half* sWb = sW + buf * (BK * W_STRIDE);
    #pragma unroll
    for (int j = 0; j < 4; j++) {
        int c = t + NTHREADS * j;      // 0..2047: 64 rows x 32 chunks of 16B
        int row = c >> 5;
        int seg = c & 31;
        cp_async16(sWb + row * W_STRIDE + seg * 8, gW + (size_t)row * OO + seg * 8);
    }
    asm volatile("cp.async.commit_group;\n" ::: "memory");
}

__global__ __launch_bounds__(NTHREADS, 1)
void k_gemm(const float* __restrict__ freqs, const float* __restrict__ phases,
            float* __restrict__ out) {
    extern __shared__ char smem_raw[];
    __half* sA = (__half*)smem_raw;                         // [2][BM][A_STRIDE]
    __half* sW = sA + 2 * BM * A_STRIDE;                    // [WSTAGES][BK][W_STRIDE]
    float* swf = (float*)(sW + WSTAGES * BK * W_STRIDE);    // [FF]
    float* spf = swf + FF;                                  // [FF]

    const int t    = threadIdx.x;
    const int lane = t & 31;
    const int warp = t >> 5;                 // 0..15
    const int bm0  = blockIdx.y * BM;
    const int bn0  = blockIdx.x * BN;
    const int wm0  = (warp >> 2) * 32;       // 4 warp-rows of 32
    const int wn0  = (warp & 3) * 64;        // 4 warp-cols of 64

    const int gr  = t >> 2;                  // A row this thread generates
    const int gfb = (t & 3) * 16;            // 16-freq block

    if (t < FF) { swf[t] = freqs[t]; spf[t] = phases[t]; }

    float acc[2][8][4];
    #pragma unroll
    for (int mt = 0; mt < 2; mt++)
        #pragma unroll
        for (int nt = 0; nt < 8; nt++)
            #pragma unroll
            for (int r = 0; r < 4; r++) acc[mt][nt][r] = 0.f;

    issueW(0, t, bn0, sW);
    issueW(1, t, bn0, sW);
    __syncthreads();                         // swf/spf visible

    // gen A(0), prefetch x(1)
    float xv = g_xT[(size_t)0 * BB + bm0 + gr];
    {
        __half* aRow = sA + (size_t)gr * A_STRIDE + gfb;
        __half2 h[8];
        #pragma unroll
        for (int j = 0; j < 8; j++) {
            int f = gfb + 2 * j;
            h[j] = __floats2half2_rn(__sinf(fmaf(swf[f],     xv, spf[f])),
                                     __sinf(fmaf(swf[f + 1], xv, spf[f + 1])));
        }
        *(uint4*)(aRow)     = *(uint4*)(h);
        *(uint4*)(aRow + 8) = *(uint4*)(h + 4);
    }
    xv = g_xT[(size_t)1 * BB + bm0 + gr];

    for (int k = 0; k < KITERS; k++) {
        const int abuf = k & 1;
        const int wbuf = k % WSTAGES;
        asm volatile("cp.async.wait_group 1;\n" ::: "memory");  // W(k) landed
        __syncthreads();   // W(k) + A(k) visible to all warps

        // ---- issue MMA batch for slab k ----
        const __half* Ab = sA + abuf * (BM * A_STRIDE);
        const __half* Wb = sW + wbuf * (BK * W_STRIDE);
        #pragma unroll
        for (int ks = 0; ks < 4; ks++) {
            uint32_t af[2][4];
            #pragma unroll
            for (int mt = 0; mt < 2; mt++) {
                uint32_t addr = smem_u32(Ab + (size_t)(wm0 + mt * 16 + (lane & 15)) * A_STRIDE
                                            + ks * 16 + (lane >> 4) * 8);
                asm volatile("ldmatrix.sync.aligned.m8n8.x4.shared.b16 {%0,%1,%2,%3}, [%4];\n"
                    : "=r"(af[mt][0]), "=r"(af[mt][1]), "=r"(af[mt][2]), "=r"(af[mt][3])
                    : "r"(addr));
            }
            uint32_t bf[8][2];
            #pragma unroll
            for (int np = 0; np < 4; np++) {
                uint32_t addr = smem_u32(Wb + (size_t)(ks * 16 + (lane & 15)) * W_STRIDE
                                            + wn0 + np * 16 + (lane >> 4) * 8);
                uint32_t b0, b1, b2, b3;
                asm volatile("ldmatrix.sync.aligned.m8n8.x4.trans.shared.b16 {%0,%1,%2,%3}, [%4];\n"
                    : "=r"(b0), "=r"(b1), "=r"(b2), "=r"(b3) : "r"(addr));
                bf[np * 2][0] = b0;     bf[np * 2][1] = b1;
                bf[np * 2 + 1][0] = b2; bf[np * 2 + 1][1] = b3;
            }
            #pragma unroll
            for (int mt = 0; mt < 2; mt++)
                #pragma unroll
                for (int nt = 0; nt < 8; nt++) {
                    asm volatile(
                        "mma.sync.aligned.m16n8k16.row.col.f32.f16.f16.f32 "
                        "{%0,%1,%2,%3}, {%4,%5,%6,%7}, {%8,%9}, {%0,%1,%2,%3};\n"
                        : "+f"(acc[mt][nt][0]), "+f"(acc[mt][nt][1]),
                          "+f"(acc[mt][nt][2]), "+f"(acc[mt][nt][3])
                        : "r"(af[mt][0]), "r"(af[mt][1]), "r"(af[mt][2]), "r"(af[mt][3]),
                          "r"(bf[nt][0]), "r"(bf[nt][1]));
                }
        }

        // ---- overlap: gen A(k+1) into other buffer (MUFU hides under HMMA) ----
        if (k + 1 < KITERS) {
            __half* aRow = sA + (abuf ^ 1) * (BM * A_STRIDE) + (size_t)gr * A_STRIDE + gfb;
            __half2 h[8];
            #pragma unroll
            for (int j = 0; j < 8; j++) {
                int f = gfb + 2 * j;
                h[j] = __floats2half2_rn(__sinf(fmaf(swf[f],     xv, spf[f])),
                                         __sinf(fmaf(swf[f + 1], xv, spf[f + 1])));
            }
            *(uint4*)(aRow)     = *(uint4*)(h);
            *(uint4*)(aRow + 8) = *(uint4*)(h + 4);
            if (k + 2 < KITERS)
                xv = g_xT[(size_t)(k + 2) * BB + bm0 + gr];
        }

        // ---- prefetch W(k+2) into stage (k+2)%3 (safe: != k%3) ----
        if (k + 2 < KITERS) issueW(k + 2, t, bn0, sW);
        else asm volatile("cp.async.commit_group;\n" ::: "memory"); // keep group count in step
    }

    // ---- epilogue: add folded bias, store fp32 ----
    #pragma unroll
    for (int mt = 0; mt < 2; mt++) {
        int row = bm0 + wm0 + mt * 16 + (lane >> 2);
        #pragma unroll
        for (int nt = 0; nt < 8; nt++) {
            int col = bn0 + wn0 + nt * 8 + (lane & 3) * 2;
            float b0 = g_biasp[col], b1 = g_biasp[col + 1];
            float2 v0 = make_float2(acc[mt][nt][0] + b0, acc[mt][nt][1] + b1);
            float2 v1 = make_float2(acc[mt][nt][2] + b0, acc[mt][nt][3] + b1);
            *(float2*)(out + (size_t)row * OO + col)       = v0;
            *(float2*)(out + (size_t)(row + 8) * OO + col) = v1;
        }
    }
}

// ---------------- launch ----------------
extern "C" void kernel_launch(void* const* d_in, const int* in_sizes, int n_in,
                              void* d_out, int out_size) {
    const float* x      = (const float*)d_in[0];  // [8192, 512]
    const float* freqs  = (const float*)d_in[1];  // [1,1,64]
    const float* phases = (const float*)d_in[2];  // [1,1,64]
    const float* beta   = (const float*)d_in[3];  // [64, 512]
    const float* lamb   = (const float*)d_in[4];  // [512, 512]
    const float* bias   = (const float*)d_in[5];  // [512]
    float* out = (float*)d_out;                   // [8192, 512] fp32

    k_prep<<<8194, 256>>>(x, freqs, phases, beta, lamb, bias);

    const size_t smem_bytes =
        (size_t)(2 * BM * A_STRIDE + WSTAGES * BK * W_STRIDE) * sizeof(__half)
        + (size_t)(2 * FF) * sizeof(float);   // 138,752 B
    cudaFuncSetAttribute(k_gemm, cudaFuncAttributeMaxDynamicSharedMemorySize,
                         (int)smem_bytes);
    dim3 grid(OO / BN, BB / BM);   // (2, 64) = 128 CTAs
    k_gemm<<<grid, NTHREADS, smem_bytes>>>(freqs, phases, out);
}